// round 1
// baseline (speedup 1.0000x reference)
#include <cuda_runtime.h>

#define NSP 100000
#define NRX 200000
#define NED 1000000
#define DM  128
#define BGR 50
#define NS_PER 2000
#define NR_PER 4000

// Scratch (static device globals — no allocation allowed in kernel_launch)
__device__ float g_hs[NSP * DM];   // species embeddings (in/out per layer)
__device__ float g_hr[NRX * DM];   // reaction embeddings
__device__ float g_mr[NRX * DM];   // messages to reactions
__device__ float g_ms[NSP * DM];   // messages to species

// ---------------------------------------------------------------------------
// Init: h_s[row] = species_table[idx] + external_table[ext]
// One warp per row, one float4 per lane.
__global__ void k_init_hs(const int* __restrict__ sidx, const int* __restrict__ ext,
                          const float* __restrict__ st, const float* __restrict__ et,
                          float* __restrict__ hs) {
    int t = blockIdx.x * blockDim.x + threadIdx.x;
    int row = t >> 5, c = t & 31;
    if (row >= NSP) return;
    int si = sidx[row], ei = ext[row];
    float4 a = ((const float4*)st)[si * 32 + c];
    float4 b = ((const float4*)et)[ei * 32 + c];
    float4 o;
    o.x = a.x + b.x; o.y = a.y + b.y; o.z = a.z + b.z; o.w = a.w + b.w;
    ((float4*)hs)[row * 32 + c] = o;
}

// Init: h_r[row] = type_table[tid] + params[row] @ W_param + b_param
__global__ void k_init_hr(const int* __restrict__ tids, const float* __restrict__ params,
                          const float* __restrict__ tt, const float* __restrict__ Wp,
                          const float* __restrict__ bp, float* __restrict__ hr) {
    int t = blockIdx.x * blockDim.x + threadIdx.x;
    int row = t >> 5, c = t & 31;
    if (row >= NRX) return;
    int ti = tids[row];
    float4 acc = ((const float4*)tt)[ti * 32 + c];
    float4 bb  = ((const float4*)bp)[c];
    acc.x += bb.x; acc.y += bb.y; acc.z += bb.z; acc.w += bb.w;
#pragma unroll
    for (int k = 0; k < 8; k++) {
        float p = params[row * 8 + k];           // warp-uniform broadcast
        float4 w = ((const float4*)Wp)[k * 32 + c];
        acc.x += p * w.x; acc.y += p * w.y; acc.z += p * w.z; acc.w += p * w.w;
    }
    ((float4*)hr)[row * 32 + c] = acc;
}

// ---------------------------------------------------------------------------
// Segment sum over edges: dst[ed[e]] += src[es[e]]  (row of 128 floats)
// One warp per edge; lane handles one float4; 128-bit vector RED to L2.
__global__ void k_seg(const float* __restrict__ src, float* __restrict__ dst,
                      const int* __restrict__ es, const int* __restrict__ ed) {
    int t = blockIdx.x * blockDim.x + threadIdx.x;
    int e = t >> 5, c = t & 31;
    if (e >= NED) return;
    int s = es[e];        // warp-uniform
    int d = ed[e];        // warp-uniform
    float4 v = ((const float4*)src)[s * 32 + c];
    float* p = dst + (size_t)d * DM + c * 4;
    asm volatile("red.global.add.v4.f32 [%0], {%1, %2, %3, %4};"
                 :: "l"(p), "f"(v.x), "f"(v.y), "f"(v.z), "f"(v.w)
                 : "memory");
}

// ---------------------------------------------------------------------------
// Fused GEMM + bias + relu, in place:
//   H[row] = relu( concat(H[row], M[row]) @ W + bias )   W: (256,128)
// Block tile: 64 rows x 128 cols, 256 threads, thread tile 8x4.
__global__ __launch_bounds__(256) void k_gemm_relu(
    float* __restrict__ H, const float* __restrict__ M,
    const float* __restrict__ W, const float* __restrict__ bias, int n) {
    __shared__ float Xs[64][32];
    __shared__ float Ws[32][128];

    int tid = threadIdx.x;
    int tx = tid & 31;       // column group: cols [4*tx, 4*tx+4)
    int ty = tid >> 5;       // row group: rows r*8 + ty
    int rowBase = blockIdx.x * 64;

    float acc[8][4];
#pragma unroll
    for (int r = 0; r < 8; r++)
#pragma unroll
        for (int j = 0; j < 4; j++) acc[r][j] = 0.f;

    for (int ch = 0; ch < 8; ch++) {
        const float* src = (ch < 4) ? H : M;
        int kb = (ch & 3) * 32;
        // load X tile (64 x 32)
#pragma unroll
        for (int i = 0; i < 8; i++) {
            int idx = tid + i * 256;
            int r = idx >> 5, kk = idx & 31;
            int gr = rowBase + r;
            Xs[r][kk] = (gr < n) ? src[gr * DM + kb + kk] : 0.f;
        }
        // load W tile (32 x 128)
        int kglob = ch * 32;
#pragma unroll
        for (int i = 0; i < 16; i++) {
            int idx = tid + i * 256;
            int kk = idx >> 7, col = idx & 127;
            Ws[kk][col] = W[(kglob + kk) * DM + col];
        }
        __syncthreads();
#pragma unroll
        for (int kk = 0; kk < 32; kk++) {
            float4 w = *(const float4*)&Ws[kk][tx * 4];
#pragma unroll
            for (int r = 0; r < 8; r++) {
                float a = Xs[r * 8 + ty][kk];   // warp-broadcast
                acc[r][0] += a * w.x;
                acc[r][1] += a * w.y;
                acc[r][2] += a * w.z;
                acc[r][3] += a * w.w;
            }
        }
        __syncthreads();
    }

    float4 b4 = ((const float4*)bias)[tx];
#pragma unroll
    for (int r = 0; r < 8; r++) {
        int gr = rowBase + r * 8 + ty;
        if (gr < n) {
            float4 o;
            o.x = fmaxf(acc[r][0] + b4.x, 0.f);
            o.y = fmaxf(acc[r][1] + b4.y, 0.f);
            o.z = fmaxf(acc[r][2] + b4.z, 0.f);
            o.w = fmaxf(acc[r][3] + b4.w, 0.f);
            ((float4*)H)[gr * 32 + tx] = o;
        }
    }
}

// ---------------------------------------------------------------------------
// Pool: out[b, 0:128] = mean over species of graph b, out[b, 128:256] = mean over reactions
// grid (4 col-chunks, B, 2 kinds), 256 threads: 8 row-groups x 32 cols.
__global__ void k_pool(const float* __restrict__ hs, const float* __restrict__ hr,
                       float* __restrict__ out) {
    int kind = blockIdx.z;               // 0 = species, 1 = reaction
    int b = blockIdx.y;
    int col = blockIdx.x * 32 + (threadIdx.x & 31);
    int g = threadIdx.x >> 5;
    const float* h = kind ? hr : hs;
    int np = kind ? NR_PER : NS_PER;
    float inv = kind ? (1.f / NR_PER) : (1.f / NS_PER);
    size_t base = (size_t)b * np * DM;
    float s = 0.f;
    for (int i = g; i < np; i += 8)
        s += h[base + (size_t)i * DM + col];
    __shared__ float red[8][32];
    red[g][threadIdx.x & 31] = s;
    __syncthreads();
    if (g == 0) {
        float tot = 0.f;
#pragma unroll
        for (int j = 0; j < 8; j++) tot += red[j][threadIdx.x & 31];
        out[b * 256 + kind * 128 + col] = tot * inv;
    }
}

// ---------------------------------------------------------------------------
extern "C" void kernel_launch(void* const* d_in, const int* in_sizes, int n_in,
                              void* d_out, int out_size) {
    const int*   species_indices = (const int*)  d_in[0];
    const int*   is_external     = (const int*)  d_in[1];
    const int*   prop_type_ids   = (const int*)  d_in[2];
    const float* prop_params     = (const float*)d_in[3];
    const int*   edge_species    = (const int*)  d_in[4];
    const int*   edge_reaction   = (const int*)  d_in[5];
    // d_in[6], d_in[7]: species_batch / reaction_batch — contiguous equal segments, implied by constants
    const float* species_table   = (const float*)d_in[8];
    const float* external_table  = (const float*)d_in[9];
    const float* type_table      = (const float*)d_in[10];
    const float* W_param         = (const float*)d_in[11];
    const float* b_param         = (const float*)d_in[12];
    const float* Wr              = (const float*)d_in[13];
    const float* br              = (const float*)d_in[14];
    const float* Ws              = (const float*)d_in[15];
    const float* bs              = (const float*)d_in[16];
    float* out = (float*)d_out;

    float *hs, *hr, *mr, *ms;
    cudaGetSymbolAddress((void**)&hs, g_hs);
    cudaGetSymbolAddress((void**)&hr, g_hr);
    cudaGetSymbolAddress((void**)&mr, g_mr);
    cudaGetSymbolAddress((void**)&ms, g_ms);

    k_init_hs<<<(NSP * 32 + 255) / 256, 256>>>(species_indices, is_external,
                                               species_table, external_table, hs);
    k_init_hr<<<(NRX * 32 + 255) / 256, 256>>>(prop_type_ids, prop_params,
                                               type_table, W_param, b_param, hr);

    const int segBlocks = (NED * 32) / 256;   // 125000
    for (int l = 0; l < 2; l++) {
        const float* Wrl = Wr + (size_t)l * 2 * DM * DM;
        const float* brl = br + (size_t)l * DM;
        const float* Wsl = Ws + (size_t)l * 2 * DM * DM;
        const float* bsl = bs + (size_t)l * DM;

        cudaMemsetAsync(mr, 0, sizeof(float) * (size_t)NRX * DM);
        k_seg<<<segBlocks, 256>>>(hs, mr, edge_species, edge_reaction);
        k_gemm_relu<<<(NRX + 63) / 64, 256>>>(hr, mr, Wrl, brl, NRX);

        cudaMemsetAsync(ms, 0, sizeof(float) * (size_t)NSP * DM);
        k_seg<<<segBlocks, 256>>>(hr, ms, edge_reaction, edge_species);
        k_gemm_relu<<<(NSP + 63) / 64, 256>>>(hs, ms, Wsl, bsl, NSP);
    }

    k_pool<<<dim3(4, BGR, 2), 256>>>(hs, hr, out);
}

// round 3
// speedup vs baseline: 1.3659x; 1.3659x over previous
#include <cuda_runtime.h>
#include <cuda_bf16.h>
#include <cstdint>

#define NSP 100000
#define NRX 200000
#define NED 1000000
#define DM  128
#define BGR 50
#define NS_PER 2000
#define NR_PER 4000

// Scratch (static device globals — no allocation allowed in kernel_launch)
__device__ float g_hs[NSP * DM];
__device__ float g_hr[NRX * DM];
__device__ float g_mr[NRX * DM];
__device__ float g_ms[NSP * DM];
// Pre-transposed, hi/lo-split weights: [which of 4][hi=0/lo=1][n=128][k=256] bf16
__device__ __nv_bfloat16 g_wt[4][2][128 * 256];

// ---------------------------------------------------------------------------
__device__ __forceinline__ uint32_t smem_u32(const void* p) {
    uint32_t a;
    asm("{ .reg .u64 t; cvta.to.shared.u64 t, %1; cvt.u32.u64 %0, t; }" : "=r"(a) : "l"(p));
    return a;
}
__device__ __forceinline__ void ldsm4(uint32_t r[4], uint32_t addr) {
    asm volatile("ldmatrix.sync.aligned.m8n8.x4.shared.b16 {%0,%1,%2,%3}, [%4];"
                 : "=r"(r[0]), "=r"(r[1]), "=r"(r[2]), "=r"(r[3]) : "r"(addr));
}
__device__ __forceinline__ void mma16816(float c[4], const uint32_t a[4],
                                         uint32_t b0, uint32_t b1) {
    asm volatile(
        "mma.sync.aligned.m16n8k16.row.col.f32.bf16.bf16.f32 "
        "{%0,%1,%2,%3}, {%4,%5,%6,%7}, {%8,%9}, {%0,%1,%2,%3};"
        : "+f"(c[0]), "+f"(c[1]), "+f"(c[2]), "+f"(c[3])
        : "r"(a[0]), "r"(a[1]), "r"(a[2]), "r"(a[3]), "r"(b0), "r"(b1));
}

// ---------------------------------------------------------------------------
// Init kernels
__global__ void k_init_hs(const int* __restrict__ sidx, const int* __restrict__ ext,
                          const float* __restrict__ st, const float* __restrict__ et,
                          float* __restrict__ hs) {
    int t = blockIdx.x * blockDim.x + threadIdx.x;
    int row = t >> 5, c = t & 31;
    if (row >= NSP) return;
    int si = sidx[row], ei = ext[row];
    float4 a = ((const float4*)st)[si * 32 + c];
    float4 b = ((const float4*)et)[ei * 32 + c];
    float4 o;
    o.x = a.x + b.x; o.y = a.y + b.y; o.z = a.z + b.z; o.w = a.w + b.w;
    ((float4*)hs)[row * 32 + c] = o;
}

__global__ void k_init_hr(const int* __restrict__ tids, const float* __restrict__ params,
                          const float* __restrict__ tt, const float* __restrict__ Wp,
                          const float* __restrict__ bp, float* __restrict__ hr) {
    int t = blockIdx.x * blockDim.x + threadIdx.x;
    int row = t >> 5, c = t & 31;
    if (row >= NRX) return;
    int ti = tids[row];
    float4 acc = ((const float4*)tt)[ti * 32 + c];
    float4 bb  = ((const float4*)bp)[c];
    acc.x += bb.x; acc.y += bb.y; acc.z += bb.z; acc.w += bb.w;
#pragma unroll
    for (int k = 0; k < 8; k++) {
        float p = params[row * 8 + k];
        float4 w = ((const float4*)Wp)[k * 32 + c];
        acc.x += p * w.x; acc.y += p * w.y; acc.z += p * w.z; acc.w += p * w.w;
    }
    ((float4*)hr)[row * 32 + c] = acc;
}

// ---------------------------------------------------------------------------
// Segment sum via 128-bit vector RED
__global__ void k_seg(const float* __restrict__ src, float* __restrict__ dst,
                      const int* __restrict__ es, const int* __restrict__ ed) {
    int t = blockIdx.x * blockDim.x + threadIdx.x;
    int e = t >> 5, c = t & 31;
    if (e >= NED) return;
    int s = es[e];
    int d = ed[e];
    float4 v = ((const float4*)src)[s * 32 + c];
    float* p = dst + (size_t)d * DM + c * 4;
    asm volatile("red.global.add.v4.f32 [%0], {%1, %2, %3, %4};"
                 :: "l"(p), "f"(v.x), "f"(v.y), "f"(v.z), "f"(v.w)
                 : "memory");
}

// ---------------------------------------------------------------------------
// W prep: transpose + hi/lo bf16 split.  g_wt[l][h][n*256+k]
// l order: 0=Wr[0], 1=Ws[0], 2=Wr[1], 3=Ws[1]
__global__ void k_prep_w(const float* __restrict__ Wr, const float* __restrict__ Ws) {
    int idx = blockIdx.x * blockDim.x + threadIdx.x;
    if (idx >= 4 * 256 * 128) return;
    int l = idx >> 15;
    int rem = idx & 32767;
    int k = rem >> 7, n = rem & 127;
    const float* src = (l & 1) ? (Ws + (size_t)(l >> 1) * 2 * DM * DM)
                               : (Wr + (size_t)(l >> 1) * 2 * DM * DM);
    float w = src[k * DM + n];
    __nv_bfloat16 hi = __float2bfloat16(w);
    float lo = w - __bfloat162float(hi);
    g_wt[l][0][n * 256 + k] = hi;
    g_wt[l][1][n * 256 + k] = __float2bfloat16(lo);
}

// ---------------------------------------------------------------------------
// Tensor-core GEMM via mma.sync (base ISA, works at compute_103):
//   H[row] = relu( concat(H,M)[row] @ W + bias ), in place.
// CTA: 256 threads (8 warps), tile 128x128, K=256 in 4 chunks of 64.
// bf16 hi/lo split: acc = Xh@Wh + Xl@Wh + Xh@Wl  (fp32 accumulate).
#define PITCH 72                     // bf16 elements per smem row (144B, 16B-aligned, conflict-free)
#define PB    (PITCH * 2)            // row pitch in bytes
#define TILEB (128 * PB)             // one 128-row tile

__global__ void __launch_bounds__(256) k_gemm_mma(
    float* __restrict__ H, const float* __restrict__ M,
    const __nv_bfloat16* __restrict__ Wth, const __nv_bfloat16* __restrict__ Wtl,
    const float* __restrict__ bias, int n)
{
    extern __shared__ char sm[];
    char* pXH = sm;
    char* pXL = sm + TILEB;
    char* pWH = sm + 2 * TILEB;
    char* pWL = sm + 3 * TILEB;
    uint32_t aXH = smem_u32(pXH), aXL = smem_u32(pXL);
    uint32_t aWH = smem_u32(pWH), aWL = smem_u32(pWL);

    int tid = threadIdx.x;
    int lane = tid & 31, wid = tid >> 5;
    int wm = (wid & 3) * 32;          // warp m offset (rows)
    int wn = (wid >> 2) * 64;         // warp n offset (cols)
    int rowBase = blockIdx.x * 128;

    // ldmatrix lane-address offsets (bytes within a tile)
    // A (m16xk16 x4): lanes 0-7: m0-7,k0 | 8-15: m8-15,k0 | 16-23: m0-7,k8 | 24-31: m8-15,k8
    uint32_t aOff = (uint32_t)(wm + (lane & 15)) * PB + ((lane >> 4) * 8) * 2;
    // B (n8xk16 pairs x4): lanes 0-7: n0-7,k0 | 8-15: n0-7,k8 | 16-23: n8-15,k0 | 24-31: n8-15,k8
    uint32_t bOff = (uint32_t)(wn + (lane & 7) + ((lane >> 4) & 1) * 8) * PB
                  + (((lane >> 3) & 1) * 8) * 2;

    float acc[2][8][4];
#pragma unroll
    for (int mt = 0; mt < 2; mt++)
#pragma unroll
        for (int nt = 0; nt < 8; nt++)
#pragma unroll
            for (int j = 0; j < 4; j++) acc[mt][nt][j] = 0.f;

    for (int ch = 0; ch < 4; ch++) {
        const float* src = (ch < 2) ? H : M;
        int kq = (ch & 1) * 16;       // float4 offset within 128-float row

        // ---- X chunk: 128 rows x 64 k fp32 -> bf16 hi/lo (32 fp32/thread) ----
#pragma unroll
        for (int i = 0; i < 8; i++) {
            int f = i * 256 + tid;
            int r = f >> 4, c = f & 15;
            int gr = rowBase + r;
            float4 v = make_float4(0.f, 0.f, 0.f, 0.f);
            if (gr < n) v = ((const float4*)src)[gr * 32 + kq + c];
            __nv_bfloat16 h0 = __float2bfloat16(v.x);
            __nv_bfloat16 h1 = __float2bfloat16(v.y);
            __nv_bfloat16 h2 = __float2bfloat16(v.z);
            __nv_bfloat16 h3 = __float2bfloat16(v.w);
            __nv_bfloat162 hh[2], ll[2];
            hh[0].x = h0; hh[0].y = h1; hh[1].x = h2; hh[1].y = h3;
            ll[0].x = __float2bfloat16(v.x - __bfloat162float(h0));
            ll[0].y = __float2bfloat16(v.y - __bfloat162float(h1));
            ll[1].x = __float2bfloat16(v.z - __bfloat162float(h2));
            ll[1].y = __float2bfloat16(v.w - __bfloat162float(h3));
            uint32_t off = (uint32_t)r * PB + c * 8;
            *(uint2*)(pXH + off) = *(uint2*)hh;
            *(uint2*)(pXL + off) = *(uint2*)ll;
        }
        // ---- W chunk: 128 n x 64 k bf16 (pre-transposed/split) ----
#pragma unroll
        for (int i = 0; i < 4; i++) {
            int f = i * 256 + tid;
            int r = f >> 3, c = f & 7;
            size_t goff = (size_t)r * 256 + ch * 64 + c * 8;
            uint32_t off = (uint32_t)r * PB + c * 16;
            *(uint4*)(pWH + off) = *(const uint4*)(Wth + goff);
            *(uint4*)(pWL + off) = *(const uint4*)(Wtl + goff);
        }
        __syncthreads();

        // ---- 3 products x 4 k16-steps ----
#pragma unroll
        for (int p = 0; p < 3; p++) {
            uint32_t aBase = (p == 1) ? aXL : aXH;
            uint32_t bBase = (p == 2) ? aWL : aWH;
#pragma unroll
            for (int ks = 0; ks < 4; ks++) {
                uint32_t aF[2][4];
                ldsm4(aF[0], aBase + aOff + ks * 32);
                ldsm4(aF[1], aBase + aOff + ks * 32 + 16 * PB);
                uint32_t bF[4][4];
#pragma unroll
                for (int q = 0; q < 4; q++)
                    ldsm4(bF[q], bBase + bOff + ks * 32 + q * 16 * PB);
#pragma unroll
                for (int mt = 0; mt < 2; mt++)
#pragma unroll
                    for (int q = 0; q < 4; q++) {
                        mma16816(acc[mt][q * 2 + 0], aF[mt], bF[q][0], bF[q][1]);
                        mma16816(acc[mt][q * 2 + 1], aF[mt], bF[q][2], bF[q][3]);
                    }
            }
        }
        __syncthreads();
    }

    // ---- epilogue: bias + relu, float2 stores ----
    int r0 = (lane >> 2);
    int c0 = (lane & 3) * 2;
#pragma unroll
    for (int mt = 0; mt < 2; mt++) {
#pragma unroll
        for (int nt = 0; nt < 8; nt++) {
            int col = wn + nt * 8 + c0;
            float2 b2 = *(const float2*)&bias[col];
            int rowA = rowBase + wm + mt * 16 + r0;
            int rowB = rowA + 8;
            if (rowA < n) {
                float2 o;
                o.x = fmaxf(acc[mt][nt][0] + b2.x, 0.f);
                o.y = fmaxf(acc[mt][nt][1] + b2.y, 0.f);
                *(float2*)&H[(size_t)rowA * DM + col] = o;
            }
            if (rowB < n) {
                float2 o;
                o.x = fmaxf(acc[mt][nt][2] + b2.x, 0.f);
                o.y = fmaxf(acc[mt][nt][3] + b2.y, 0.f);
                *(float2*)&H[(size_t)rowB * DM + col] = o;
            }
        }
    }
}

// ---------------------------------------------------------------------------
// Pool
__global__ void k_pool(const float* __restrict__ hs, const float* __restrict__ hr,
                       float* __restrict__ out) {
    int kind = blockIdx.z;
    int b = blockIdx.y;
    int col = blockIdx.x * 32 + (threadIdx.x & 31);
    int g = threadIdx.x >> 5;
    const float* h = kind ? hr : hs;
    int np = kind ? NR_PER : NS_PER;
    float inv = kind ? (1.f / NR_PER) : (1.f / NS_PER);
    size_t base = (size_t)b * np * DM;
    float s = 0.f;
    for (int i = g; i < np; i += 8)
        s += h[base + (size_t)i * DM + col];
    __shared__ float red[8][32];
    red[g][threadIdx.x & 31] = s;
    __syncthreads();
    if (g == 0) {
        float tot = 0.f;
#pragma unroll
        for (int j = 0; j < 8; j++) tot += red[j][threadIdx.x & 31];
        out[b * 256 + kind * 128 + col] = tot * inv;
    }
}

// ---------------------------------------------------------------------------
extern "C" void kernel_launch(void* const* d_in, const int* in_sizes, int n_in,
                              void* d_out, int out_size) {
    const int*   species_indices = (const int*)  d_in[0];
    const int*   is_external     = (const int*)  d_in[1];
    const int*   prop_type_ids   = (const int*)  d_in[2];
    const float* prop_params     = (const float*)d_in[3];
    const int*   edge_species    = (const int*)  d_in[4];
    const int*   edge_reaction   = (const int*)  d_in[5];
    const float* species_table   = (const float*)d_in[8];
    const float* external_table  = (const float*)d_in[9];
    const float* type_table      = (const float*)d_in[10];
    const float* W_param         = (const float*)d_in[11];
    const float* b_param         = (const float*)d_in[12];
    const float* Wr              = (const float*)d_in[13];
    const float* br              = (const float*)d_in[14];
    const float* Ws              = (const float*)d_in[15];
    const float* bs              = (const float*)d_in[16];
    float* out = (float*)d_out;

    float *hs, *hr, *mr, *ms;
    __nv_bfloat16* wt;
    cudaGetSymbolAddress((void**)&hs, g_hs);
    cudaGetSymbolAddress((void**)&hr, g_hr);
    cudaGetSymbolAddress((void**)&mr, g_mr);
    cudaGetSymbolAddress((void**)&ms, g_ms);
    cudaGetSymbolAddress((void**)&wt, g_wt);

    const int GEMM_SMEM = 4 * TILEB;   // 73728 B
    cudaFuncSetAttribute(k_gemm_mma, cudaFuncAttributeMaxDynamicSharedMemorySize, GEMM_SMEM);

    k_init_hs<<<(NSP * 32 + 255) / 256, 256>>>(species_indices, is_external,
                                               species_table, external_table, hs);
    k_init_hr<<<(NRX * 32 + 255) / 256, 256>>>(prop_type_ids, prop_params,
                                               type_table, W_param, b_param, hr);
    k_prep_w<<<512, 256>>>(Wr, Ws);

    const int segBlocks = (NED * 32) / 256;
    const size_t WSZ = (size_t)2 * 128 * 256;
    for (int l = 0; l < 2; l++) {
        const float* brl = br + (size_t)l * DM;
        const float* bsl = bs + (size_t)l * DM;
        const __nv_bfloat16* WrH = wt + (size_t)(2 * l + 0) * WSZ;
        const __nv_bfloat16* WrL = WrH + 128 * 256;
        const __nv_bfloat16* WsH = wt + (size_t)(2 * l + 1) * WSZ;
        const __nv_bfloat16* WsL = WsH + 128 * 256;

        cudaMemsetAsync(mr, 0, sizeof(float) * (size_t)NRX * DM);
        k_seg<<<segBlocks, 256>>>(hs, mr, edge_species, edge_reaction);
        k_gemm_mma<<<(NRX + 127) / 128, 256, GEMM_SMEM>>>(hr, mr, WrH, WrL, brl, NRX);

        cudaMemsetAsync(ms, 0, sizeof(float) * (size_t)NSP * DM);
        k_seg<<<segBlocks, 256>>>(hr, ms, edge_reaction, edge_species);
        k_gemm_mma<<<(NSP + 127) / 128, 256, GEMM_SMEM>>>(hs, ms, WsH, WsL, bsl, NSP);
    }

    k_pool<<<dim3(4, BGR, 2), 256>>>(hs, hr, out);
}

// round 4
// speedup vs baseline: 1.5574x; 1.1402x over previous
#include <cuda_runtime.h>
#include <cuda_bf16.h>
#include <cstdint>

#define NSP 100000
#define NRX 200000
#define NED 1000000
#define DM  128
#define BGR 50
#define NS_PER 2000
#define NR_PER 4000

// Scratch buffers (static device globals)
__device__ float g_hsA[NSP * DM];
__device__ float g_hsB[NSP * DM];
__device__ float g_hrA[NRX * DM];
__device__ float g_hrB[NRX * DM];
__device__ float g_y[NSP * DM];    // Y = relu?(h_s) @ Wr2
__device__ float g_z[NRX * DM];    // Z = relu(h_r)  @ Ws2
// Pre-transposed, hi/lo-split weights: [which of 4][hi=0/lo=1][n=128][k=256] bf16
__device__ __nv_bfloat16 g_wt[4][2][128 * 256];

// ---------------------------------------------------------------------------
__device__ __forceinline__ uint32_t smem_u32(const void* p) {
    uint32_t a;
    asm("{ .reg .u64 t; cvta.to.shared.u64 t, %1; cvt.u32.u64 %0, t; }" : "=r"(a) : "l"(p));
    return a;
}
__device__ __forceinline__ void ldsm4(uint32_t r[4], uint32_t addr) {
    asm volatile("ldmatrix.sync.aligned.m8n8.x4.shared.b16 {%0,%1,%2,%3}, [%4];"
                 : "=r"(r[0]), "=r"(r[1]), "=r"(r[2]), "=r"(r[3]) : "r"(addr));
}
__device__ __forceinline__ void mma16816(float c[4], const uint32_t a[4],
                                         uint32_t b0, uint32_t b1) {
    asm volatile(
        "mma.sync.aligned.m16n8k16.row.col.f32.bf16.bf16.f32 "
        "{%0,%1,%2,%3}, {%4,%5,%6,%7}, {%8,%9}, {%0,%1,%2,%3};"
        : "+f"(c[0]), "+f"(c[1]), "+f"(c[2]), "+f"(c[3])
        : "r"(a[0]), "r"(a[1]), "r"(a[2]), "r"(a[3]), "r"(b0), "r"(b1));
}

// ---------------------------------------------------------------------------
// Init kernels
__global__ void k_init_hs(const int* __restrict__ sidx, const int* __restrict__ ext,
                          const float* __restrict__ st, const float* __restrict__ et,
                          float* __restrict__ hs) {
    int t = blockIdx.x * blockDim.x + threadIdx.x;
    int row = t >> 5, c = t & 31;
    if (row >= NSP) return;
    int si = sidx[row], ei = ext[row];
    float4 a = ((const float4*)st)[si * 32 + c];
    float4 b = ((const float4*)et)[ei * 32 + c];
    float4 o;
    o.x = a.x + b.x; o.y = a.y + b.y; o.z = a.z + b.z; o.w = a.w + b.w;
    ((float4*)hs)[row * 32 + c] = o;
}

__global__ void k_init_hr(const int* __restrict__ tids, const float* __restrict__ params,
                          const float* __restrict__ tt, const float* __restrict__ Wp,
                          const float* __restrict__ bp, float* __restrict__ hr) {
    int t = blockIdx.x * blockDim.x + threadIdx.x;
    int row = t >> 5, c = t & 31;
    if (row >= NRX) return;
    int ti = tids[row];
    float4 acc = ((const float4*)tt)[ti * 32 + c];
    float4 bb  = ((const float4*)bp)[c];
    acc.x += bb.x; acc.y += bb.y; acc.z += bb.z; acc.w += bb.w;
#pragma unroll
    for (int k = 0; k < 8; k++) {
        float p = params[row * 8 + k];
        float4 w = ((const float4*)Wp)[k * 32 + c];
        acc.x += p * w.x; acc.y += p * w.y; acc.z += p * w.z; acc.w += p * w.w;
    }
    ((float4*)hr)[row * 32 + c] = acc;
}

// ---------------------------------------------------------------------------
// Segment sum, 4 edges per warp for MLP: dst[ed[e]] += src[es[e]]
__global__ void k_seg4(const float* __restrict__ src, float* __restrict__ dst,
                       const int* __restrict__ es, const int* __restrict__ ed) {
    int t = blockIdx.x * blockDim.x + threadIdx.x;
    int w = t >> 5, lane = t & 31;
    int e0 = w * 4;
    if (e0 >= NED) return;
    int4 s4 = *(const int4*)(es + e0);
    int4 d4 = *(const int4*)(ed + e0);
    const float4* src4 = (const float4*)src;
    float4 v0 = src4[(size_t)s4.x * 32 + lane];
    float4 v1 = src4[(size_t)s4.y * 32 + lane];
    float4 v2 = src4[(size_t)s4.z * 32 + lane];
    float4 v3 = src4[(size_t)s4.w * 32 + lane];
    float* p0 = dst + (size_t)d4.x * DM + lane * 4;
    float* p1 = dst + (size_t)d4.y * DM + lane * 4;
    float* p2 = dst + (size_t)d4.z * DM + lane * 4;
    float* p3 = dst + (size_t)d4.w * DM + lane * 4;
    asm volatile("red.global.add.v4.f32 [%0], {%1, %2, %3, %4};"
                 :: "l"(p0), "f"(v0.x), "f"(v0.y), "f"(v0.z), "f"(v0.w) : "memory");
    asm volatile("red.global.add.v4.f32 [%0], {%1, %2, %3, %4};"
                 :: "l"(p1), "f"(v1.x), "f"(v1.y), "f"(v1.z), "f"(v1.w) : "memory");
    asm volatile("red.global.add.v4.f32 [%0], {%1, %2, %3, %4};"
                 :: "l"(p2), "f"(v2.x), "f"(v2.y), "f"(v2.z), "f"(v2.w) : "memory");
    asm volatile("red.global.add.v4.f32 [%0], {%1, %2, %3, %4};"
                 :: "l"(p3), "f"(v3.x), "f"(v3.y), "f"(v3.z), "f"(v3.w) : "memory");
}

// ---------------------------------------------------------------------------
// W prep: transpose + hi/lo bf16 split.  g_wt[l][h][n*256+k]
// l order: 0=Wr[0], 1=Ws[0], 2=Wr[1], 3=Ws[1]
// k in [0,128) = W1 (h part), k in [128,256) = W2 (msg part)
__global__ void k_prep_w(const float* __restrict__ Wr, const float* __restrict__ Ws) {
    int idx = blockIdx.x * blockDim.x + threadIdx.x;
    if (idx >= 4 * 256 * 128) return;
    int l = idx >> 15;
    int rem = idx & 32767;
    int k = rem >> 7, n = rem & 127;
    const float* src = (l & 1) ? (Ws + (size_t)(l >> 1) * 2 * DM * DM)
                               : (Wr + (size_t)(l >> 1) * 2 * DM * DM);
    float w = src[k * DM + n];
    __nv_bfloat16 hi = __float2bfloat16(w);
    float lo = w - __bfloat162float(hi);
    g_wt[l][0][n * 256 + k] = hi;
    g_wt[l][1][n * 256 + k] = __float2bfloat16(lo);
}

// ---------------------------------------------------------------------------
// Tensor-core GEMM (K=128):  D[row] = relu?(X[row]) @ W[koff:koff+128] (+ bias)
// CTA: 256 threads (8 warps), tile 128x128, K=128 in 2 chunks of 64.
// bf16 hi/lo split: acc = Xh@Wh + Xl@Wh + Xh@Wl  (fp32 accumulate).
#define PITCH 72
#define PB    (PITCH * 2)
#define TILEB (128 * PB)

template<bool RELU_IN, bool HAS_BIAS>
__global__ void __launch_bounds__(256) k_gemm_mma(
    float* __restrict__ D, const float* __restrict__ X,
    const __nv_bfloat16* __restrict__ Wth, const __nv_bfloat16* __restrict__ Wtl,
    const float* __restrict__ bias, int n, int koff)
{
    extern __shared__ char sm[];
    char* pXH = sm;
    char* pXL = sm + TILEB;
    char* pWH = sm + 2 * TILEB;
    char* pWL = sm + 3 * TILEB;
    uint32_t aXH = smem_u32(pXH), aXL = smem_u32(pXL);
    uint32_t aWH = smem_u32(pWH), aWL = smem_u32(pWL);

    int tid = threadIdx.x;
    int lane = tid & 31, wid = tid >> 5;
    int wm = (wid & 3) * 32;
    int wn = (wid >> 2) * 64;
    int rowBase = blockIdx.x * 128;

    uint32_t aOff = (uint32_t)(wm + (lane & 15)) * PB + ((lane >> 4) * 8) * 2;
    uint32_t bOff = (uint32_t)(wn + (lane & 7) + ((lane >> 4) & 1) * 8) * PB
                  + (((lane >> 3) & 1) * 8) * 2;

    float acc[2][8][4];
#pragma unroll
    for (int mt = 0; mt < 2; mt++)
#pragma unroll
        for (int nt = 0; nt < 8; nt++)
#pragma unroll
            for (int j = 0; j < 4; j++) acc[mt][nt][j] = 0.f;

#pragma unroll
    for (int ch = 0; ch < 2; ch++) {
        int kq = ch * 16;
        // ---- X chunk: 128 rows x 64 k fp32 -> (relu) -> bf16 hi/lo ----
#pragma unroll
        for (int i = 0; i < 8; i++) {
            int f = i * 256 + tid;
            int r = f >> 4, c = f & 15;
            int gr = rowBase + r;
            float4 v = make_float4(0.f, 0.f, 0.f, 0.f);
            if (gr < n) v = ((const float4*)X)[gr * 32 + kq + c];
            if (RELU_IN) {
                v.x = fmaxf(v.x, 0.f); v.y = fmaxf(v.y, 0.f);
                v.z = fmaxf(v.z, 0.f); v.w = fmaxf(v.w, 0.f);
            }
            __nv_bfloat16 h0 = __float2bfloat16(v.x);
            __nv_bfloat16 h1 = __float2bfloat16(v.y);
            __nv_bfloat16 h2 = __float2bfloat16(v.z);
            __nv_bfloat16 h3 = __float2bfloat16(v.w);
            __nv_bfloat162 hh[2], ll[2];
            hh[0].x = h0; hh[0].y = h1; hh[1].x = h2; hh[1].y = h3;
            ll[0].x = __float2bfloat16(v.x - __bfloat162float(h0));
            ll[0].y = __float2bfloat16(v.y - __bfloat162float(h1));
            ll[1].x = __float2bfloat16(v.z - __bfloat162float(h2));
            ll[1].y = __float2bfloat16(v.w - __bfloat162float(h3));
            uint32_t off = (uint32_t)r * PB + c * 8;
            *(uint2*)(pXH + off) = *(uint2*)hh;
            *(uint2*)(pXL + off) = *(uint2*)ll;
        }
        // ---- W chunk: 128 n x 64 k bf16 ----
#pragma unroll
        for (int i = 0; i < 4; i++) {
            int f = i * 256 + tid;
            int r = f >> 3, c = f & 7;
            size_t goff = (size_t)r * 256 + koff + ch * 64 + c * 8;
            uint32_t off = (uint32_t)r * PB + c * 16;
            *(uint4*)(pWH + off) = *(const uint4*)(Wth + goff);
            *(uint4*)(pWL + off) = *(const uint4*)(Wtl + goff);
        }
        __syncthreads();

#pragma unroll
        for (int p = 0; p < 3; p++) {
            uint32_t aBase = (p == 1) ? aXL : aXH;
            uint32_t bBase = (p == 2) ? aWL : aWH;
#pragma unroll
            for (int ks = 0; ks < 4; ks++) {
                uint32_t aF[2][4];
                ldsm4(aF[0], aBase + aOff + ks * 32);
                ldsm4(aF[1], aBase + aOff + ks * 32 + 16 * PB);
                uint32_t bF[4][4];
#pragma unroll
                for (int q = 0; q < 4; q++)
                    ldsm4(bF[q], bBase + bOff + ks * 32 + q * 16 * PB);
#pragma unroll
                for (int mt = 0; mt < 2; mt++)
#pragma unroll
                    for (int q = 0; q < 4; q++) {
                        mma16816(acc[mt][q * 2 + 0], aF[mt], bF[q][0], bF[q][1]);
                        mma16816(acc[mt][q * 2 + 1], aF[mt], bF[q][2], bF[q][3]);
                    }
            }
        }
        __syncthreads();
    }

    // ---- epilogue: (+bias), NO relu (deferred to consumers) ----
    int r0 = (lane >> 2);
    int c0 = (lane & 3) * 2;
#pragma unroll
    for (int mt = 0; mt < 2; mt++) {
#pragma unroll
        for (int nt = 0; nt < 8; nt++) {
            int col = wn + nt * 8 + c0;
            float2 b2 = make_float2(0.f, 0.f);
            if (HAS_BIAS) b2 = *(const float2*)&bias[col];
            int rowA = rowBase + wm + mt * 16 + r0;
            int rowB = rowA + 8;
            if (rowA < n) {
                float2 o;
                o.x = acc[mt][nt][0] + b2.x;
                o.y = acc[mt][nt][1] + b2.y;
                *(float2*)&D[(size_t)rowA * DM + col] = o;
            }
            if (rowB < n) {
                float2 o;
                o.x = acc[mt][nt][2] + b2.x;
                o.y = acc[mt][nt][3] + b2.y;
                *(float2*)&D[(size_t)rowB * DM + col] = o;
            }
        }
    }
}

// ---------------------------------------------------------------------------
// Pool with deferred relu on inputs
__global__ void k_pool(const float* __restrict__ hs, const float* __restrict__ hr,
                       float* __restrict__ out) {
    int kind = blockIdx.z;
    int b = blockIdx.y;
    int col = blockIdx.x * 32 + (threadIdx.x & 31);
    int g = threadIdx.x >> 5;
    const float* h = kind ? hr : hs;
    int np = kind ? NR_PER : NS_PER;
    float inv = kind ? (1.f / NR_PER) : (1.f / NS_PER);
    size_t base = (size_t)b * np * DM;
    float s = 0.f;
    for (int i = g; i < np; i += 8)
        s += fmaxf(h[base + (size_t)i * DM + col], 0.f);
    __shared__ float red[8][32];
    red[g][threadIdx.x & 31] = s;
    __syncthreads();
    if (g == 0) {
        float tot = 0.f;
#pragma unroll
        for (int j = 0; j < 8; j++) tot += red[j][threadIdx.x & 31];
        out[b * 256 + kind * 128 + col] = tot * inv;
    }
}

// ---------------------------------------------------------------------------
extern "C" void kernel_launch(void* const* d_in, const int* in_sizes, int n_in,
                              void* d_out, int out_size) {
    const int*   species_indices = (const int*)  d_in[0];
    const int*   is_external     = (const int*)  d_in[1];
    const int*   prop_type_ids   = (const int*)  d_in[2];
    const float* prop_params     = (const float*)d_in[3];
    const int*   edge_species    = (const int*)  d_in[4];
    const int*   edge_reaction   = (const int*)  d_in[5];
    const float* species_table   = (const float*)d_in[8];
    const float* external_table  = (const float*)d_in[9];
    const float* type_table      = (const float*)d_in[10];
    const float* W_param         = (const float*)d_in[11];
    const float* b_param         = (const float*)d_in[12];
    const float* Wr              = (const float*)d_in[13];
    const float* br              = (const float*)d_in[14];
    const float* Ws              = (const float*)d_in[15];
    const float* bs              = (const float*)d_in[16];
    float* out = (float*)d_out;

    float *hsA, *hsB, *hrA, *hrB, *y, *z;
    __nv_bfloat16* wt;
    cudaGetSymbolAddress((void**)&hsA, g_hsA);
    cudaGetSymbolAddress((void**)&hsB, g_hsB);
    cudaGetSymbolAddress((void**)&hrA, g_hrA);
    cudaGetSymbolAddress((void**)&hrB, g_hrB);
    cudaGetSymbolAddress((void**)&y, g_y);
    cudaGetSymbolAddress((void**)&z, g_z);
    cudaGetSymbolAddress((void**)&wt, g_wt);

    const int GEMM_SMEM = 4 * TILEB;
    cudaFuncSetAttribute(k_gemm_mma<false, false>, cudaFuncAttributeMaxDynamicSharedMemorySize, GEMM_SMEM);
    cudaFuncSetAttribute(k_gemm_mma<false, true>,  cudaFuncAttributeMaxDynamicSharedMemorySize, GEMM_SMEM);
    cudaFuncSetAttribute(k_gemm_mma<true, false>,  cudaFuncAttributeMaxDynamicSharedMemorySize, GEMM_SMEM);
    cudaFuncSetAttribute(k_gemm_mma<true, true>,   cudaFuncAttributeMaxDynamicSharedMemorySize, GEMM_SMEM);

    k_init_hs<<<(NSP * 32 + 255) / 256, 256>>>(species_indices, is_external,
                                               species_table, external_table, hsA);
    k_init_hr<<<(NRX * 32 + 255) / 256, 256>>>(prop_type_ids, prop_params,
                                               type_table, W_param, b_param, hrA);
    k_prep_w<<<512, 256>>>(Wr, Ws);

    const int segBlocks = (NED / 4 * 32 + 255) / 256;   // 31250
    const int gS = (NSP + 127) / 128, gR = (NRX + 127) / 128;
    const size_t WSZ = (size_t)2 * 128 * 256;

    // ---- layer 0 (inputs have no relu) ----
    {
        const __nv_bfloat16* WrH = wt + 0 * WSZ;  const __nv_bfloat16* WrL = WrH + 128 * 256;
        const __nv_bfloat16* WsH = wt + 1 * WSZ;  const __nv_bfloat16* WsL = WsH + 128 * 256;
        // Y = hs @ Wr2 ; A_r = hr @ Wr1 + br ; A_r += seg(Y)
        k_gemm_mma<false, false><<<gS, 256, GEMM_SMEM>>>(y,   hsA, WrH, WrL, nullptr, NSP, 128);
        k_gemm_mma<false, true ><<<gR, 256, GEMM_SMEM>>>(hrB, hrA, WrH, WrL, br,      NRX, 0);
        k_seg4<<<segBlocks, 256>>>(y, hrB, edge_species, edge_reaction);
        // Z = relu(A_r) @ Ws2 ; A_s = hs @ Ws1 + bs ; A_s += seg(Z)
        k_gemm_mma<true,  false><<<gR, 256, GEMM_SMEM>>>(z,   hrB, WsH, WsL, nullptr, NRX, 128);
        k_gemm_mma<false, true ><<<gS, 256, GEMM_SMEM>>>(hsB, hsA, WsH, WsL, bs,      NSP, 0);
        k_seg4<<<segBlocks, 256>>>(z, hsB, edge_reaction, edge_species);
    }
    // ---- layer 1 (inputs need relu) ----
    {
        const __nv_bfloat16* WrH = wt + 2 * WSZ;  const __nv_bfloat16* WrL = WrH + 128 * 256;
        const __nv_bfloat16* WsH = wt + 3 * WSZ;  const __nv_bfloat16* WsL = WsH + 128 * 256;
        const float* br1 = br + DM;
        const float* bs1 = bs + DM;
        k_gemm_mma<true, false><<<gS, 256, GEMM_SMEM>>>(y,   hsB, WrH, WrL, nullptr, NSP, 128);
        k_gemm_mma<true, true ><<<gR, 256, GEMM_SMEM>>>(hrA, hrB, WrH, WrL, br1,     NRX, 0);
        k_seg4<<<segBlocks, 256>>>(y, hrA, edge_species, edge_reaction);
        k_gemm_mma<true, false><<<gR, 256, GEMM_SMEM>>>(z,   hrA, WsH, WsL, nullptr, NRX, 128);
        k_gemm_mma<true, true ><<<gS, 256, GEMM_SMEM>>>(hsA, hsB, WsH, WsL, bs1,     NSP, 0);
        k_seg4<<<segBlocks, 256>>>(z, hsA, edge_reaction, edge_species);
    }

    k_pool<<<dim3(4, BGR, 2), 256>>>(hsA, hrA, out);
}